// round 11
// baseline (speedup 1.0000x reference)
#include <cuda_runtime.h>
#include <cuda_bf16.h>
#include <math.h>
#include <stdint.h>

// Problem constants
#define HID   1024
#define NH    16
#define DH    64
#define SEQ   4096
#define BATCH 2
#define WIN   512
#define MTOT  (BATCH*SEQ)          // 8192 tokens
#define XELEMS ((size_t)MTOT*HID)  // 8M
#define WELEMS ((size_t)HID*HID)   // 1M

// ---------------------------------------------------------------------------
// Scratch (__device__ globals; no allocations allowed)
// ---------------------------------------------------------------------------
__device__ __nv_bfloat16 g_Xhi[XELEMS];
__device__ __nv_bfloat16 g_Xlo[XELEMS];
__device__ __nv_bfloat16 g_Whi[4 * WELEMS];   // q,k,v,o
__device__ __nv_bfloat16 g_Wlo[4 * WELEMS];
__device__ __nv_bfloat16 g_Qhi[XELEMS];       // [b,h,s,d], pre-scaled by 1/8
__device__ __nv_bfloat16 g_Qlo[XELEMS];
__device__ __nv_bfloat16 g_Khi[XELEMS];
__device__ __nv_bfloat16 g_Klo[XELEMS];
__device__ __nv_bfloat16 g_Vhi[XELEMS];
__device__ __nv_bfloat16 g_Vlo[XELEMS];
__device__ __nv_bfloat16 g_Ahi[XELEMS];       // attn out, [token, HID] split
__device__ __nv_bfloat16 g_Alo[XELEMS];

// ---------------------------------------------------------------------------
// PTX helpers (baseline PTX only — compute_103-safe)
// ---------------------------------------------------------------------------
__device__ __forceinline__ uint32_t smem_u32(const void* p) {
    uint32_t a;
    asm("{ .reg .u64 t; cvta.to.shared.u64 t, %1; cvt.u32.u64 %0, t; }" : "=r"(a) : "l"(p));
    return a;
}
__device__ __forceinline__ void cp16(uint32_t dst, const void* src) {
    asm volatile("cp.async.cg.shared.global [%0], [%1], 16;" :: "r"(dst), "l"(src));
}
#define CP_COMMIT() asm volatile("cp.async.commit_group;" ::: "memory")
template <int N>
__device__ __forceinline__ void cp_wait() {
    asm volatile("cp.async.wait_group %0;" :: "n"(N) : "memory");
}
__device__ __forceinline__ void ldsm_x4(uint32_t& r0, uint32_t& r1, uint32_t& r2, uint32_t& r3, uint32_t a) {
    asm volatile("ldmatrix.sync.aligned.m8n8.x4.shared.b16 {%0,%1,%2,%3}, [%4];"
                 : "=r"(r0), "=r"(r1), "=r"(r2), "=r"(r3) : "r"(a));
}
__device__ __forceinline__ void ldsm_x4_t(uint32_t& r0, uint32_t& r1, uint32_t& r2, uint32_t& r3, uint32_t a) {
    asm volatile("ldmatrix.sync.aligned.m8n8.x4.trans.shared.b16 {%0,%1,%2,%3}, [%4];"
                 : "=r"(r0), "=r"(r1), "=r"(r2), "=r"(r3) : "r"(a));
}
__device__ __forceinline__ void mma16816(float* c, const uint32_t* a, const uint32_t* b) {
    asm volatile(
        "mma.sync.aligned.m16n8k16.row.col.f32.bf16.bf16.f32 "
        "{%0,%1,%2,%3}, {%4,%5,%6,%7}, {%8,%9}, {%0,%1,%2,%3};"
        : "+f"(c[0]), "+f"(c[1]), "+f"(c[2]), "+f"(c[3])
        : "r"(a[0]), "r"(a[1]), "r"(a[2]), "r"(a[3]), "r"(b[0]), "r"(b[1]));
}
// pack two floats -> bf16x2 (lo = a, hi = b)
__device__ __forceinline__ uint32_t bfpack(float a, float b) {
    uint32_t r;
    asm("cvt.rn.bf16x2.f32 %0, %1, %2;" : "=r"(r) : "f"(b), "f"(a));
    return r;
}

// ---------------------------------------------------------------------------
// fp32 -> bf16 hi/lo split of x and the 4 weight matrices
// ---------------------------------------------------------------------------
__global__ __launch_bounds__(256)
void split_kernel(const float* __restrict__ x,
                  const float* __restrict__ Wq, const float* __restrict__ Wk,
                  const float* __restrict__ Wv, const float* __restrict__ Wo)
{
    size_t t = (size_t)blockIdx.x * 256 + threadIdx.x;
    size_t e = t * 4;
    const float* src;
    __nv_bfloat16 *dh, *dl;
    if (e < XELEMS) {
        src = x + e; dh = g_Xhi + e; dl = g_Xlo + e;
    } else {
        size_t r = e - XELEMS;
        int w = (int)(r >> 20);
        size_t off = r & (WELEMS - 1);
        const float* Ws[4] = {Wq, Wk, Wv, Wo};
        src = Ws[w] + off;
        dh = g_Whi + (size_t)w * WELEMS + off;
        dl = g_Wlo + (size_t)w * WELEMS + off;
    }
    float4 v = *(const float4*)src;
    __nv_bfloat16 h0 = __float2bfloat16(v.x), h1 = __float2bfloat16(v.y);
    __nv_bfloat16 h2 = __float2bfloat16(v.z), h3 = __float2bfloat16(v.w);
    ushort4 uh, ul;
    uh.x = __bfloat16_as_ushort(h0); uh.y = __bfloat16_as_ushort(h1);
    uh.z = __bfloat16_as_ushort(h2); uh.w = __bfloat16_as_ushort(h3);
    ul.x = __bfloat16_as_ushort(__float2bfloat16(v.x - __bfloat162float(h0)));
    ul.y = __bfloat16_as_ushort(__float2bfloat16(v.y - __bfloat162float(h1)));
    ul.z = __bfloat16_as_ushort(__float2bfloat16(v.z - __bfloat162float(h2)));
    ul.w = __bfloat16_as_ushort(__float2bfloat16(v.w - __bfloat162float(h3)));
    *(ushort4*)dh = uh;
    *(ushort4*)dl = ul;
}

// ---------------------------------------------------------------------------
// bf16-split GEMM via mma.sync: C[m,n] = sum_k A[m,k]*W[n,k]
// 128x128 CTA tile, 128 threads (4 warps, 2x2), warp tile 64x64, BK=32.
// B-frags resident per ks; A-frags loaded per-i (low register pressure).
// MODE 0: fp32 output.  MODE 1: bf16 hi/lo output to [b,h,s,d] (scaled).
// ---------------------------------------------------------------------------
#define BM 128
#define BN 128
#define BK 32
#define RSB 80
#define TSB (128 * RSB)
#define BUFB (4 * TSB)
#define GSMEM (2 * BUFB)
#define NCH (HID / BK)
#define GTHREADS 128

__device__ __forceinline__ void load_chunk(
    uint32_t sbuf, int tid,
    const __nv_bfloat16* __restrict__ Ahi, const __nv_bfloat16* __restrict__ Alo,
    const __nv_bfloat16* __restrict__ Bhi, const __nv_bfloat16* __restrict__ Blo,
    int m0, int n0, int k0)
{
#pragma unroll
    for (int i = 0; i < 16; i++) {
        const int tile = i >> 2;                 // 0:Ahi 1:Alo 2:Bhi 3:Blo
        const int idx = tid + (i & 3) * GTHREADS; // 0..511
        const int r = idx >> 2;
        const int c = idx & 3;
        const __nv_bfloat16* base =
            (tile == 0) ? Ahi : (tile == 1) ? Alo : (tile == 2) ? Bhi : Blo;
        const int row0 = (tile < 2) ? m0 : n0;
        const __nv_bfloat16* src = base + (size_t)(row0 + r) * HID + k0 + c * 8;
        cp16(sbuf + tile * TSB + r * RSB + c * 16, src);
    }
}

template <int MODE>
__device__ __forceinline__ void gemm_body(
    const __nv_bfloat16* __restrict__ Ahi, const __nv_bfloat16* __restrict__ Alo,
    const __nv_bfloat16* __restrict__ Bhi, const __nv_bfloat16* __restrict__ Blo,
    float* __restrict__ C, __nv_bfloat16* __restrict__ Chi,
    __nv_bfloat16* __restrict__ Clo, float scale)
{
    extern __shared__ char smem[];
    const uint32_t sb = smem_u32(smem);
    const int tid = threadIdx.x;
    const int lane = tid & 31;
    const int wid = tid >> 5;            // 0..3
    const int wm0 = (wid & 1) * 64;
    const int wn0 = (wid >> 1) * 64;
    const int m0 = blockIdx.x * BM;
    const int n0 = blockIdx.y * BN;

    float acc[4][8][4];
#pragma unroll
    for (int i = 0; i < 4; i++)
#pragma unroll
        for (int j = 0; j < 8; j++)
#pragma unroll
            for (int v = 0; v < 4; v++) acc[i][j][v] = 0.0f;

    load_chunk(sb, tid, Ahi, Alo, Bhi, Blo, m0, n0, 0);
    CP_COMMIT();

#pragma unroll 1
    for (int ch = 0; ch < NCH; ch++) {
        cp_wait<0>();
        __syncthreads();   // chunk ch visible; other buffer free
        if (ch + 1 < NCH) {
            load_chunk(sb + ((ch + 1) & 1) * BUFB, tid, Ahi, Alo, Bhi, Blo,
                       m0, n0, (ch + 1) * BK);
            CP_COMMIT();
        }

        const uint32_t sbuf = sb + (ch & 1) * BUFB;
        const uint32_t sAh = sbuf;
        const uint32_t sAl = sbuf + TSB;
        const uint32_t sBh = sbuf + 2 * TSB;
        const uint32_t sBl = sbuf + 3 * TSB;

#pragma unroll
        for (int ks = 0; ks < 2; ks++) {
            // B fragments for all 8 n8-blocks stay resident (32 regs)
            uint32_t bh[8][2], bl[8][2];
#pragma unroll
            for (int jj = 0; jj < 4; jj++) {
                const int nrow = wn0 + 8 * (jj * 2 + ((lane >> 4) & 1)) + (lane & 7);
                const int kcolb = (ks * 16 + 8 * ((lane >> 3) & 1)) * 2;
                const uint32_t off = (uint32_t)nrow * RSB + kcolb;
                ldsm_x4(bh[jj*2][0], bh[jj*2][1], bh[jj*2+1][0], bh[jj*2+1][1], sBh + off);
                ldsm_x4(bl[jj*2][0], bl[jj*2][1], bl[jj*2+1][0], bl[jj*2+1][1], sBl + off);
            }
            // A fragments loaded per-i (8 regs live at a time)
            const int arow = wm0 + (lane & 15);
            const int acolb = (ks * 16 + 8 * ((lane >> 4) & 1)) * 2;
#pragma unroll
            for (int i = 0; i < 4; i++) {
                uint32_t ah[4], al[4];
                const uint32_t off = (uint32_t)(arow + i * 16) * RSB + acolb;
                ldsm_x4(ah[0], ah[1], ah[2], ah[3], sAh + off);
                ldsm_x4(al[0], al[1], al[2], al[3], sAl + off);
#pragma unroll
                for (int j = 0; j < 8; j++) {
                    mma16816(acc[i][j], ah, bh[j]);
                    mma16816(acc[i][j], ah, bl[j]);
                    mma16816(acc[i][j], al, bh[j]);
                }
            }
        }
        // no trailing sync — next iteration's barrier covers buffer reuse
    }

    // direct-store epilogue
    const int frow = lane >> 2;
    const int fcol = 2 * (lane & 3);
#pragma unroll
    for (int i = 0; i < 4; i++) {
#pragma unroll
        for (int j = 0; j < 8; j++) {
            const int m = m0 + wm0 + i * 16 + frow;
            const int n = n0 + wn0 + j * 8 + fcol;
            if (MODE == 1) {
                const int b = m >> 12, s = m & (SEQ - 1);
                const int h = n >> 6, d = n & 63;
                const size_t base0 = (((size_t)(b * NH + h) * SEQ + s) * DH) + d;
                const size_t base1 = base0 + 8 * DH;   // row m+8, same b
                float c0 = acc[i][j][0] * scale, c1 = acc[i][j][1] * scale;
                float c2 = acc[i][j][2] * scale, c3 = acc[i][j][3] * scale;
                __nv_bfloat16 h0 = __float2bfloat16(c0), h1 = __float2bfloat16(c1);
                __nv_bfloat16 h2 = __float2bfloat16(c2), h3 = __float2bfloat16(c3);
                ushort2 u0, u1, v0, v1;
                u0.x = __bfloat16_as_ushort(h0); u0.y = __bfloat16_as_ushort(h1);
                u1.x = __bfloat16_as_ushort(h2); u1.y = __bfloat16_as_ushort(h3);
                v0.x = __bfloat16_as_ushort(__float2bfloat16(c0 - __bfloat162float(h0)));
                v0.y = __bfloat16_as_ushort(__float2bfloat16(c1 - __bfloat162float(h1)));
                v1.x = __bfloat16_as_ushort(__float2bfloat16(c2 - __bfloat162float(h2)));
                v1.y = __bfloat16_as_ushort(__float2bfloat16(c3 - __bfloat162float(h3)));
                *(ushort2*)(Chi + base0) = u0;
                *(ushort2*)(Chi + base1) = u1;
                *(ushort2*)(Clo + base0) = v0;
                *(ushort2*)(Clo + base1) = v1;
            } else {
                float* cp = C + (size_t)m * HID + n;
                *(float2*)cp = make_float2(acc[i][j][0], acc[i][j][1]);
                *(float2*)(cp + 8 * HID) = make_float2(acc[i][j][2], acc[i][j][3]);
            }
        }
    }
}

__global__ __launch_bounds__(GTHREADS, 2)
void qkv_mma_kernel()
{
    const int z = blockIdx.z;
    __nv_bfloat16* Chi = (z == 0) ? g_Qhi : (z == 1) ? g_Khi : g_Vhi;
    __nv_bfloat16* Clo = (z == 0) ? g_Qlo : (z == 1) ? g_Klo : g_Vlo;
    const float scale = (z == 0) ? 0.125f : 1.0f;
    gemm_body<1>(g_Xhi, g_Xlo,
                 g_Whi + (size_t)z * WELEMS, g_Wlo + (size_t)z * WELEMS,
                 nullptr, Chi, Clo, scale);
}

__global__ __launch_bounds__(GTHREADS, 2)
void oproj_mma_kernel(float* __restrict__ out)
{
    gemm_body<0>(g_Ahi, g_Alo, g_Whi + 3 * WELEMS, g_Wlo + 3 * WELEMS,
                 out, nullptr, nullptr, 1.0f);
}

// ---------------------------------------------------------------------------
// Flash attention via mma.sync. CTA = 128 queries x 1 head. 8 warps x 16 rows.
// KV chunks of 64 keys, double-buffered cp.async, one sync per chunk.
// ---------------------------------------------------------------------------
#define QT 128
#define TRB 144                       // smem tile row bytes (128 data + 16 pad)
#define TILEB (64 * TRB)              // 9216
#define STAGEB (4 * TILEB)            // 36864 (Khi,Klo,Vhi,Vlo)
#define ASMEM (2 * STAGEB + 512)

__device__ __forceinline__ void load_kv(
    uint32_t sb, int tid, int st, int c, size_t headoff,
    const int* __restrict__ attn_mask, int b)
{
#pragma unroll
    for (int i = 0; i < 8; i++) {
        const int idx = tid + i * 256;       // 0..2047
        const int t = idx >> 9;              // tile 0..3
        const int r = (idx >> 3) & 63;
        const int cc = idx & 7;
        const __nv_bfloat16* base =
            (t == 0) ? g_Khi : (t == 1) ? g_Klo : (t == 2) ? g_Vhi : g_Vlo;
        const __nv_bfloat16* src = base + headoff + (size_t)(c * 64 + r) * DH + cc * 8;
        cp16(sb + st * STAGEB + t * TILEB + r * TRB + cc * 16, src);
    }
    if (tid < 16)
        cp16(sb + 2 * STAGEB + st * 256 + tid * 16, attn_mask + b * SEQ + c * 64 + tid * 4);
    CP_COMMIT();
}

__global__ __launch_bounds__(256, 2)
void attn_mma_kernel(const int* __restrict__ attn_mask)
{
    extern __shared__ char smem[];
    const uint32_t sb = smem_u32(smem);
    const int tid = threadIdx.x;
    const int lane = tid & 31;
    const int wid = tid >> 5;
    const int qb = blockIdx.x;
    const int h = blockIdx.y;
    const int b = blockIdx.z;
    const int q0 = qb * QT;
    const size_t headoff = (size_t)(b * NH + h) * SEQ * DH;

    // ---- stage Q tile (hi/lo) into stage-0 buffer, read frags, then reuse ----
#pragma unroll
    for (int i = 0; i < 8; i++) {
        const int idx = tid + i * 256;       // 0..2047
        const int t = idx >> 10;             // 0 hi, 1 lo
        const int r = (idx >> 3) & 127;
        const int cc = idx & 7;
        const __nv_bfloat16* base = t ? g_Qlo : g_Qhi;
        cp16(sb + t * 18432 + r * TRB + cc * 16,
             base + headoff + (size_t)(q0 + r) * DH + cc * 8);
    }
    CP_COMMIT();
    cp_wait<0>();
    __syncthreads();

    uint32_t qh[4][4], ql[4][4];
    {
        const int arow = wid * 16 + (lane & 15);
#pragma unroll
        for (int ks = 0; ks < 4; ks++) {
            const uint32_t off = (uint32_t)arow * TRB + (ks * 16 + 8 * ((lane >> 4) & 1)) * 2;
            ldsm_x4(qh[ks][0], qh[ks][1], qh[ks][2], qh[ks][3], sb + off);
            ldsm_x4(ql[ks][0], ql[ks][1], ql[ks][2], ql[ks][3], sb + 18432 + off);
        }
    }
    __syncthreads();   // done with Q staging area

    const int r0g = q0 + wid * 16 + (lane >> 2);
    const int r1g = r0g + 8;

    float m0r = -1e4f, m1r = -1e4f, l0 = 0.0f, l1 = 0.0f;
    float o[8][4];
#pragma unroll
    for (int j = 0; j < 8; j++)
#pragma unroll
        for (int v = 0; v < 4; v++) o[j][v] = 0.0f;

    const int clo = (2 * qb >= 8) ? (2 * qb - 8) : 0;
    const int chi = 2 * qb + 1;

    load_kv(sb, tid, 0, clo, headoff, attn_mask, b);

#pragma unroll 1
    for (int c = clo; c <= chi; c++) {
        const int st = (c - clo) & 1;
        cp_wait<0>();
        __syncthreads();   // chunk c visible; stage st^1 free
        if (c < chi)
            load_kv(sb, tid, st ^ 1, c + 1, headoff, attn_mask, b);

        const uint32_t kb = sb + st * STAGEB;

        // ---- S = Q K^T (3 split terms) ----
        float p[8][4];
#pragma unroll
        for (int j = 0; j < 8; j++)
#pragma unroll
            for (int v = 0; v < 4; v++) p[j][v] = 0.0f;

#pragma unroll
        for (int ks = 0; ks < 4; ks++) {
            uint32_t bh[8][2], bl[8][2];
#pragma unroll
            for (int jj = 0; jj < 4; jj++) {
                const int nrow = 16 * jj + 8 * ((lane >> 4) & 1) + (lane & 7);
                const int kcolb = (ks * 16 + 8 * ((lane >> 3) & 1)) * 2;
                const uint32_t off = (uint32_t)nrow * TRB + kcolb;
                ldsm_x4(bh[jj*2][0], bh[jj*2][1], bh[jj*2+1][0], bh[jj*2+1][1], kb + off);
                ldsm_x4(bl[jj*2][0], bl[jj*2][1], bl[jj*2+1][0], bl[jj*2+1][1], kb + TILEB + off);
            }
#pragma unroll
            for (int j = 0; j < 8; j++) {
                mma16816(p[j], qh[ks], bh[j]);
                mma16816(p[j], qh[ks], bl[j]);
                mma16816(p[j], ql[ks], bh[j]);
            }
        }

        // ---- mask + online softmax ----
        const int* mk = (const int*)(smem + 2 * STAGEB + st * 256);
        const int c64 = c * 64;
#pragma unroll
        for (int j = 0; j < 8; j++) {
            const int kloc = j * 8 + 2 * (lane & 3);
            const int kg = c64 + kloc;
            const int mv0 = mk[kloc], mv1 = mk[kloc + 1];
            if (!(kg     <= r0g && kg     >= r0g - (WIN-1) && mv0)) p[j][0] = -1e30f;
            if (!(kg + 1 <= r0g && kg + 1 >= r0g - (WIN-1) && mv1)) p[j][1] = -1e30f;
            if (!(kg     <= r1g && kg     >= r1g - (WIN-1) && mv0)) p[j][2] = -1e30f;
            if (!(kg + 1 <= r1g && kg + 1 >= r1g - (WIN-1) && mv1)) p[j][3] = -1e30f;
        }
        float mx0 = -1e30f, mx1 = -1e30f;
#pragma unroll
        for (int j = 0; j < 8; j++) {
            mx0 = fmaxf(mx0, fmaxf(p[j][0], p[j][1]));
            mx1 = fmaxf(mx1, fmaxf(p[j][2], p[j][3]));
        }
        mx0 = fmaxf(mx0, __shfl_xor_sync(0xffffffffu, mx0, 1));
        mx0 = fmaxf(mx0, __shfl_xor_sync(0xffffffffu, mx0, 2));
        mx1 = fmaxf(mx1, __shfl_xor_sync(0xffffffffu, mx1, 1));
        mx1 = fmaxf(mx1, __shfl_xor_sync(0xffffffffu, mx1, 2));

        const float mn0 = fmaxf(m0r, mx0);
        const float mn1 = fmaxf(m1r, mx1);
        const float cr0 = __expf(m0r - mn0);
        const float cr1 = __expf(m1r - mn1);
        m0r = mn0; m1r = mn1;
        l0 *= cr0; l1 *= cr1;
#pragma unroll
        for (int j = 0; j < 8; j++) {
            o[j][0] *= cr0; o[j][1] *= cr0;
            o[j][2] *= cr1; o[j][3] *= cr1;
        }
        float s0 = 0.0f, s1 = 0.0f;
#pragma unroll
        for (int j = 0; j < 8; j++) {
            p[j][0] = __expf(p[j][0] - mn0); s0 += p[j][0];
            p[j][1] = __expf(p[j][1] - mn0); s0 += p[j][1];
            p[j][2] = __expf(p[j][2] - mn1); s1 += p[j][2];
            p[j][3] = __expf(p[j][3] - mn1); s1 += p[j][3];
        }
        // quad-reduce the denominator partial sums (O sums over all quad keys)
        s0 += __shfl_xor_sync(0xffffffffu, s0, 1);
        s0 += __shfl_xor_sync(0xffffffffu, s0, 2);
        s1 += __shfl_xor_sync(0xffffffffu, s1, 1);
        s1 += __shfl_xor_sync(0xffffffffu, s1, 2);
        l0 += s0; l1 += s1;

        // ---- O += P V (3 split terms) ----
#pragma unroll
        for (int ks2 = 0; ks2 < 4; ks2++) {
            uint32_t ahp[4], alp[4];
            {
                const float p00 = p[2*ks2][0],   p01 = p[2*ks2][1];
                const float p02 = p[2*ks2][2],   p03 = p[2*ks2][3];
                const float p10 = p[2*ks2+1][0], p11 = p[2*ks2+1][1];
                const float p12 = p[2*ks2+1][2], p13 = p[2*ks2+1][3];
                ahp[0] = bfpack(p00, p01);
                ahp[1] = bfpack(p02, p03);
                ahp[2] = bfpack(p10, p11);
                ahp[3] = bfpack(p12, p13);
                const __nv_bfloat162* hp0 = (const __nv_bfloat162*)&ahp[0];
                const __nv_bfloat162* hp1 = (const __nv_bfloat162*)&ahp[1];
                const __nv_bfloat162* hp2 = (const __nv_bfloat162*)&ahp[2];
                const __nv_bfloat162* hp3 = (const __nv_bfloat162*)&ahp[3];
                alp[0] = bfpack(p00 - __bfloat162float(hp0->x), p01 - __bfloat162float(hp0->y));
                alp[1] = bfpack(p02 - __bfloat162float(hp1->x), p03 - __bfloat162float(hp1->y));
                alp[2] = bfpack(p10 - __bfloat162float(hp2->x), p11 - __bfloat162float(hp2->y));
                alp[3] = bfpack(p12 - __bfloat162float(hp3->x), p13 - __bfloat162float(hp3->y));
            }
            uint32_t bvh[8][2], bvl[8][2];
#pragma unroll
            for (int jj = 0; jj < 4; jj++) {
                const int vrow = 16 * ks2 + (lane & 7) + 8 * ((lane >> 3) & 1);
                const int colb = (2 * jj + (lane >> 4)) * 16;
                const uint32_t off = (uint32_t)vrow * TRB + colb;
                ldsm_x4_t(bvh[jj*2][0], bvh[jj*2][1], bvh[jj*2+1][0], bvh[jj*2+1][1],
                          kb + 2 * TILEB + off);
                ldsm_x4_t(bvl[jj*2][0], bvl[jj*2][1], bvl[jj*2+1][0], bvl[jj*2+1][1],
                          kb + 3 * TILEB + off);
            }
#pragma unroll
            for (int j = 0; j < 8; j++) {
                mma16816(o[j], ahp, bvh[j]);
                mma16816(o[j], ahp, bvl[j]);
                mma16816(o[j], alp, bvh[j]);
            }
        }
        // no trailing sync — next iteration's barrier covers stage reuse
    }

    // ---- normalize + write bf16 hi/lo to [token, HID] ----
    const float i0 = 1.0f / fmaxf(l0, 1e-30f);
    const float i1 = 1.0f / fmaxf(l1, 1e-30f);
    const size_t t0 = (size_t)(b * SEQ + r0g) * HID + h * DH;
    const size_t t1 = (size_t)(b * SEQ + r1g) * HID + h * DH;
#pragma unroll
    for (int j = 0; j < 8; j++) {
        const int d = j * 8 + 2 * (lane & 3);
        float a0 = o[j][0] * i0, a1 = o[j][1] * i0;
        float a2 = o[j][2] * i1, a3 = o[j][3] * i1;
        __nv_bfloat16 h0 = __float2bfloat16(a0), h1 = __float2bfloat16(a1);
        __nv_bfloat16 h2 = __float2bfloat16(a2), h3 = __float2bfloat16(a3);
        ushort2 u0, u1, v0, v1;
        u0.x = __bfloat16_as_ushort(h0); u0.y = __bfloat16_as_ushort(h1);
        u1.x = __bfloat16_as_ushort(h2); u1.y = __bfloat16_as_ushort(h3);
        v0.x = __bfloat16_as_ushort(__float2bfloat16(a0 - __bfloat162float(h0)));
        v0.y = __bfloat16_as_ushort(__float2bfloat16(a1 - __bfloat162float(h1)));
        v1.x = __bfloat16_as_ushort(__float2bfloat16(a2 - __bfloat162float(h2)));
        v1.y = __bfloat16_as_ushort(__float2bfloat16(a3 - __bfloat162float(h3)));
        *(ushort2*)(g_Ahi + t0 + d) = u0;
        *(ushort2*)(g_Ahi + t1 + d) = u1;
        *(ushort2*)(g_Alo + t0 + d) = v0;
        *(ushort2*)(g_Alo + t1 + d) = v1;
    }
}

// ---------------------------------------------------------------------------
// Launch
// ---------------------------------------------------------------------------
extern "C" void kernel_launch(void* const* d_in, const int* in_sizes, int n_in,
                              void* d_out, int out_size)
{
    const float* x    = (const float*)d_in[0];
    const int*   mask = (const int*)  d_in[1];
    const float* Wq   = (const float*)d_in[2];
    const float* Wk   = (const float*)d_in[3];
    const float* Wv   = (const float*)d_in[4];
    const float* Wo   = (const float*)d_in[5];
    float* out = (float*)d_out;

    static bool attr_set = false;
    if (!attr_set) {
        cudaFuncSetAttribute(qkv_mma_kernel,   cudaFuncAttributeMaxDynamicSharedMemorySize, GSMEM);
        cudaFuncSetAttribute(oproj_mma_kernel, cudaFuncAttributeMaxDynamicSharedMemorySize, GSMEM);
        cudaFuncSetAttribute(attn_mma_kernel,  cudaFuncAttributeMaxDynamicSharedMemorySize, ASMEM);
        attr_set = true;
    }

    split_kernel<<<12288, 256>>>(x, Wq, Wk, Wv, Wo);

    dim3 qgrid(MTOT / BM, HID / BN, 3);
    qkv_mma_kernel<<<qgrid, GTHREADS, GSMEM>>>();

    dim3 agrid(SEQ / QT, NH, BATCH);
    attn_mma_kernel<<<agrid, 256, ASMEM>>>(mask);

    dim3 ogrid(MTOT / BM, HID / BN, 1);
    oproj_mma_kernel<<<ogrid, GTHREADS, GSMEM>>>(out);
}

// round 13
// speedup vs baseline: 1.2016x; 1.2016x over previous
#include <cuda_runtime.h>
#include <cuda_bf16.h>
#include <math.h>
#include <stdint.h>

// Problem constants
#define HID   1024
#define NH    16
#define DH    64
#define SEQ   4096
#define BATCH 2
#define WIN   512
#define MTOT  (BATCH*SEQ)          // 8192 tokens
#define XELEMS ((size_t)MTOT*HID)  // 8M

// Tiled operand layout: tile = 128 rows x 32 k-cols, padded rows of 80B,
// 10240 B contiguous — EXACT image of the GEMM smem tile.
#define TILEBYTES 10240
#define NCH 32                     // HID / 32 k-chunks
#define NMB 64                     // MTOT / 128 row-blocks
#define NNB 8                      // HID / 128 col-blocks (weights)

// ---------------------------------------------------------------------------
// Scratch (__device__ globals; no allocations allowed)
// ---------------------------------------------------------------------------
__device__ char g_XhiT[(size_t)NMB * NCH * TILEBYTES];   // x split, tiled
__device__ char g_XloT[(size_t)NMB * NCH * TILEBYTES];
__device__ char g_WhiT[(size_t)4 * NNB * NCH * TILEBYTES]; // q,k,v,o weights, tiled
__device__ char g_WloT[(size_t)4 * NNB * NCH * TILEBYTES];
__device__ char g_AhiT[(size_t)NMB * NCH * TILEBYTES];   // attn out, tiled
__device__ char g_AloT[(size_t)NMB * NCH * TILEBYTES];
__device__ __nv_bfloat16 g_Qhi[XELEMS];       // [b,h,s,d], pre-scaled by 1/8
__device__ __nv_bfloat16 g_Qlo[XELEMS];
__device__ __nv_bfloat16 g_Khi[XELEMS];
__device__ __nv_bfloat16 g_Klo[XELEMS];
__device__ __nv_bfloat16 g_Vhi[XELEMS];
__device__ __nv_bfloat16 g_Vlo[XELEMS];

// ---------------------------------------------------------------------------
// PTX helpers (baseline PTX only — compute_103-safe, sm_90-family features)
// ---------------------------------------------------------------------------
__device__ __forceinline__ uint32_t smem_u32(const void* p) {
    uint32_t a;
    asm("{ .reg .u64 t; cvta.to.shared.u64 t, %1; cvt.u32.u64 %0, t; }" : "=r"(a) : "l"(p));
    return a;
}
__device__ __forceinline__ void cp16(uint32_t dst, const void* src) {
    asm volatile("cp.async.cg.shared.global [%0], [%1], 16;" :: "r"(dst), "l"(src));
}
#define CP_COMMIT() asm volatile("cp.async.commit_group;" ::: "memory")
template <int N>
__device__ __forceinline__ void cp_wait() {
    asm volatile("cp.async.wait_group %0;" :: "n"(N) : "memory");
}
__device__ __forceinline__ void ldsm_x4(uint32_t& r0, uint32_t& r1, uint32_t& r2, uint32_t& r3, uint32_t a) {
    asm volatile("ldmatrix.sync.aligned.m8n8.x4.shared.b16 {%0,%1,%2,%3}, [%4];"
                 : "=r"(r0), "=r"(r1), "=r"(r2), "=r"(r3) : "r"(a));
}
__device__ __forceinline__ void ldsm_x4_t(uint32_t& r0, uint32_t& r1, uint32_t& r2, uint32_t& r3, uint32_t a) {
    asm volatile("ldmatrix.sync.aligned.m8n8.x4.trans.shared.b16 {%0,%1,%2,%3}, [%4];"
                 : "=r"(r0), "=r"(r1), "=r"(r2), "=r"(r3) : "r"(a));
}
__device__ __forceinline__ void mma16816(float* c, const uint32_t* a, const uint32_t* b) {
    asm volatile(
        "mma.sync.aligned.m16n8k16.row.col.f32.bf16.bf16.f32 "
        "{%0,%1,%2,%3}, {%4,%5,%6,%7}, {%8,%9}, {%0,%1,%2,%3};"
        : "+f"(c[0]), "+f"(c[1]), "+f"(c[2]), "+f"(c[3])
        : "r"(a[0]), "r"(a[1]), "r"(a[2]), "r"(a[3]), "r"(b[0]), "r"(b[1]));
}
__device__ __forceinline__ uint32_t bfpack(float a, float b) {
    uint32_t r;
    asm("cvt.rn.bf16x2.f32 %0, %1, %2;" : "=r"(r) : "f"(b), "f"(a));
    return r;
}
// --- bulk-copy (1D TMA) + mbarrier ---
#define MBAR_INIT(a, n) asm volatile("mbarrier.init.shared.b64 [%0], %1;" :: "r"(a), "r"(n) : "memory")
#define FENCE_ASYNC()   asm volatile("fence.proxy.async.shared::cta;" ::: "memory")
__device__ __forceinline__ void mbar_expect_tx(uint32_t mbar, uint32_t bytes) {
    asm volatile("mbarrier.arrive.expect_tx.shared.b64 _, [%0], %1;" :: "r"(mbar), "r"(bytes) : "memory");
}
__device__ __forceinline__ void bulk_cp(uint32_t dst, const void* src, uint32_t bytes, uint32_t mbar) {
    asm volatile("cp.async.bulk.shared::cta.global.mbarrier::complete_tx::bytes [%0], [%1], %2, [%3];"
                 :: "r"(dst), "l"(src), "r"(bytes), "r"(mbar) : "memory");
}
__device__ __forceinline__ void mbar_wait(uint32_t addr, uint32_t parity) {
    asm volatile(
        "{ .reg .pred P1;\n"
        "W%=: mbarrier.try_wait.parity.acquire.cta.shared::cta.b64 P1, [%0], %1;\n"
        "@P1 bra.uni D%=;\n bra.uni W%=;\n D%=: }"
        :: "r"(addr), "r"(parity) : "memory");
}

// ---------------------------------------------------------------------------
// fp32 -> bf16 hi/lo split of x and the 4 weight matrices, TILED output.
// Block = one 128x32 tile. 256 threads; thread t: 4 rows x 4 cols each.
// ---------------------------------------------------------------------------
__global__ __launch_bounds__(256)
void split_kernel(const float* __restrict__ x,
                  const float* __restrict__ Wq, const float* __restrict__ Wk,
                  const float* __restrict__ Wv, const float* __restrict__ Wo)
{
    const int bid = blockIdx.x;
    const int tid = threadIdx.x;
    const int c4 = (tid & 7) * 4;

    const float* srcbase;
    char *dh, *dl;
    if (bid < NMB * NCH) {                      // X tiles
        const int mb = bid >> 5, kc = bid & 31;
        srcbase = x + (size_t)(mb * 128) * HID + kc * 32;
        dh = g_XhiT + (size_t)bid * TILEBYTES;
        dl = g_XloT + (size_t)bid * TILEBYTES;
    } else {                                     // W tiles
        const int wb = bid - NMB * NCH;
        const int w = wb >> 8;                   // 256 tiles per weight
        const int rem = wb & 255;
        const int nb = rem >> 5, kc = rem & 31;
        const float* Ws[4] = {Wq, Wk, Wv, Wo};
        srcbase = Ws[w] + (size_t)(nb * 128) * HID + kc * 32;
        dh = g_WhiT + (size_t)wb * TILEBYTES;
        dl = g_WloT + (size_t)wb * TILEBYTES;
    }
#pragma unroll
    for (int i = 0; i < 4; i++) {
        const int r = (tid >> 3) + i * 32;       // FULL 128 rows (round-12 bug fix)
        float4 v = *(const float4*)(srcbase + (size_t)r * HID + c4);
        __nv_bfloat16 h0 = __float2bfloat16(v.x), h1 = __float2bfloat16(v.y);
        __nv_bfloat16 h2 = __float2bfloat16(v.z), h3 = __float2bfloat16(v.w);
        ushort4 uh, ul;
        uh.x = __bfloat16_as_ushort(h0); uh.y = __bfloat16_as_ushort(h1);
        uh.z = __bfloat16_as_ushort(h2); uh.w = __bfloat16_as_ushort(h3);
        ul.x = __bfloat16_as_ushort(__float2bfloat16(v.x - __bfloat162float(h0)));
        ul.y = __bfloat16_as_ushort(__float2bfloat16(v.y - __bfloat162float(h1)));
        ul.z = __bfloat16_as_ushort(__float2bfloat16(v.z - __bfloat162float(h2)));
        ul.w = __bfloat16_as_ushort(__float2bfloat16(v.w - __bfloat162float(h3)));
        const uint32_t off = (uint32_t)r * 80 + c4 * 2;
        *(ushort4*)(dh + off) = uh;
        *(ushort4*)(dl + off) = ul;
    }
}

// ---------------------------------------------------------------------------
// bf16-split GEMM via mma.sync: C[m,n] = sum_k A[m,k]*W[n,k]
// 128x128 CTA tile, 128 threads (4 warps, 2x2), warp tile 64x64, BK=32.
// Tile loads via cp.async.bulk (1D TMA) + mbarrier; tiles are pre-padded
// 10240B images in global -> one bulk op per tile.
// ---------------------------------------------------------------------------
#define BM 128
#define BN 128
#define RSB 80
#define TSB TILEBYTES               // 10240
#define BUFB (4 * TSB)              // 40960 (Ahi,Alo,Bhi,Blo)
#define GSMEM (2 * BUFB + 64)
#define GTHREADS 128

template <int MODE>
__device__ __forceinline__ void gemm_body(
    const char* __restrict__ AhiT, const char* __restrict__ AloT,
    const char* __restrict__ BhiT, const char* __restrict__ BloT,
    float* __restrict__ C, __nv_bfloat16* __restrict__ Chi,
    __nv_bfloat16* __restrict__ Clo, float scale)
{
    extern __shared__ char smem[];
    const uint32_t sb = smem_u32(smem);
    const int tid = threadIdx.x;
    const int lane = tid & 31;
    const int wid = tid >> 5;            // 0..3
    const int wm0 = (wid & 1) * 64;
    const int wn0 = (wid >> 1) * 64;
    const int m0 = blockIdx.x * BM;
    const int n0 = blockIdx.y * BN;
    const size_t atb = (size_t)(m0 >> 7) * NCH;   // A tile row-block base
    const size_t btb = (size_t)(n0 >> 7) * NCH;   // B tile col-block base
    const uint32_t mb0 = sb + 2 * BUFB;

    if (tid == 0) { MBAR_INIT(mb0, 1); MBAR_INIT(mb0 + 8, 1); }
    FENCE_ASYNC();
    __syncthreads();

    float acc[4][8][4];
#pragma unroll
    for (int i = 0; i < 4; i++)
#pragma unroll
        for (int j = 0; j < 8; j++)
#pragma unroll
            for (int v = 0; v < 4; v++) acc[i][j][v] = 0.0f;

    // issue chunk 0
    if (tid == 0) {
        mbar_expect_tx(mb0, BUFB);
        bulk_cp(sb,           AhiT + (atb + 0) * TILEBYTES, TILEBYTES, mb0);
        bulk_cp(sb + TSB,     AloT + (atb + 0) * TILEBYTES, TILEBYTES, mb0);
        bulk_cp(sb + 2 * TSB, BhiT + (btb + 0) * TILEBYTES, TILEBYTES, mb0);
        bulk_cp(sb + 3 * TSB, BloT + (btb + 0) * TILEBYTES, TILEBYTES, mb0);
    }

    int ph0 = 0, ph1 = 0;

#pragma unroll 1
    for (int ch = 0; ch < NCH; ch++) {
        const int buf = ch & 1;
        if (buf == 0) { mbar_wait(mb0, ph0); ph0 ^= 1; }
        else          { mbar_wait(mb0 + 8, ph1); ph1 ^= 1; }
        __syncthreads();   // all warps done with buf^1's previous chunk
        if (tid == 0 && ch + 1 < NCH) {
            const uint32_t nbuf = sb + (buf ^ 1) * BUFB;
            const uint32_t nm = mb0 + (buf ^ 1) * 8;
            mbar_expect_tx(nm, BUFB);
            bulk_cp(nbuf,           AhiT + (atb + ch + 1) * TILEBYTES, TILEBYTES, nm);
            bulk_cp(nbuf + TSB,     AloT + (atb + ch + 1) * TILEBYTES, TILEBYTES, nm);
            bulk_cp(nbuf + 2 * TSB, BhiT + (btb + ch + 1) * TILEBYTES, TILEBYTES, nm);
            bulk_cp(nbuf + 3 * TSB, BloT + (btb + ch + 1) * TILEBYTES, TILEBYTES, nm);
        }

        const uint32_t sbuf = sb + buf * BUFB;
        const uint32_t sAh = sbuf;
        const uint32_t sAl = sbuf + TSB;
        const uint32_t sBh = sbuf + 2 * TSB;
        const uint32_t sBl = sbuf + 3 * TSB;

#pragma unroll
        for (int ks = 0; ks < 2; ks++) {
            const int arow = wm0 + (lane & 15);
            const int acolb = (ks * 16 + 8 * ((lane >> 4) & 1)) * 2;
            uint32_t ah[4][4], al[4][4];
#pragma unroll
            for (int i = 0; i < 4; i++) {
                const uint32_t off = (uint32_t)(arow + i * 16) * RSB + acolb;
                ldsm_x4(ah[i][0], ah[i][1], ah[i][2], ah[i][3], sAh + off);
                ldsm_x4(al[i][0], al[i][1], al[i][2], al[i][3], sAl + off);
            }
            uint32_t bh[8][2], bl[8][2];
#pragma unroll
            for (int jj = 0; jj < 4; jj++) {
                const int nrow = wn0 + 8 * (jj * 2 + ((lane >> 4) & 1)) + (lane & 7);
                const int kcolb = (ks * 16 + 8 * ((lane >> 3) & 1)) * 2;
                const uint32_t off = (uint32_t)nrow * RSB + kcolb;
                ldsm_x4(bh[jj*2][0], bh[jj*2][1], bh[jj*2+1][0], bh[jj*2+1][1], sBh + off);
                ldsm_x4(bl[jj*2][0], bl[jj*2][1], bl[jj*2+1][0], bl[jj*2+1][1], sBl + off);
            }
#pragma unroll
            for (int i = 0; i < 4; i++)
#pragma unroll
                for (int j = 0; j < 8; j++) {
                    mma16816(acc[i][j], ah[i], bh[j]);
                    mma16816(acc[i][j], ah[i], bl[j]);
                    mma16816(acc[i][j], al[i], bh[j]);
                }
        }
        // no trailing sync — next iteration's wait+sync covers buffer reuse
    }

    // direct-store epilogue
    const int frow = lane >> 2;
    const int fcol = 2 * (lane & 3);
#pragma unroll
    for (int i = 0; i < 4; i++) {
#pragma unroll
        for (int j = 0; j < 8; j++) {
            const int m = m0 + wm0 + i * 16 + frow;
            const int n = n0 + wn0 + j * 8 + fcol;
            if (MODE == 1) {
                const int b = m >> 12, s = m & (SEQ - 1);
                const int h = n >> 6, d = n & 63;
                const size_t base0 = (((size_t)(b * NH + h) * SEQ + s) * DH) + d;
                const size_t base1 = base0 + 8 * DH;   // row m+8, same b
                float c0 = acc[i][j][0] * scale, c1 = acc[i][j][1] * scale;
                float c2 = acc[i][j][2] * scale, c3 = acc[i][j][3] * scale;
                __nv_bfloat16 h0 = __float2bfloat16(c0), h1 = __float2bfloat16(c1);
                __nv_bfloat16 h2 = __float2bfloat16(c2), h3 = __float2bfloat16(c3);
                ushort2 u0, u1, v0, v1;
                u0.x = __bfloat16_as_ushort(h0); u0.y = __bfloat16_as_ushort(h1);
                u1.x = __bfloat16_as_ushort(h2); u1.y = __bfloat16_as_ushort(h3);
                v0.x = __bfloat16_as_ushort(__float2bfloat16(c0 - __bfloat162float(h0)));
                v0.y = __bfloat16_as_ushort(__float2bfloat16(c1 - __bfloat162float(h1)));
                v1.x = __bfloat16_as_ushort(__float2bfloat16(c2 - __bfloat162float(h2)));
                v1.y = __bfloat16_as_ushort(__float2bfloat16(c3 - __bfloat162float(h3)));
                *(ushort2*)(Chi + base0) = u0;
                *(ushort2*)(Chi + base1) = u1;
                *(ushort2*)(Clo + base0) = v0;
                *(ushort2*)(Clo + base1) = v1;
            } else {
                float* cp = C + (size_t)m * HID + n;
                *(float2*)cp = make_float2(acc[i][j][0], acc[i][j][1]);
                *(float2*)(cp + 8 * HID) = make_float2(acc[i][j][2], acc[i][j][3]);
            }
        }
    }
}

__global__ __launch_bounds__(GTHREADS, 2)
void qkv_mma_kernel()
{
    const int z = blockIdx.z;
    __nv_bfloat16* Chi = (z == 0) ? g_Qhi : (z == 1) ? g_Khi : g_Vhi;
    __nv_bfloat16* Clo = (z == 0) ? g_Qlo : (z == 1) ? g_Klo : g_Vlo;
    const float scale = (z == 0) ? 0.125f : 1.0f;
    const size_t wsz = (size_t)NNB * NCH * TILEBYTES;
    gemm_body<1>(g_XhiT, g_XloT,
                 g_WhiT + (size_t)z * wsz, g_WloT + (size_t)z * wsz,
                 nullptr, Chi, Clo, scale);
}

__global__ __launch_bounds__(GTHREADS, 2)
void oproj_mma_kernel(float* __restrict__ out)
{
    const size_t wsz = (size_t)NNB * NCH * TILEBYTES;
    gemm_body<0>(g_AhiT, g_AloT,
                 g_WhiT + 3 * wsz, g_WloT + 3 * wsz,
                 out, nullptr, nullptr, 1.0f);
}

// ---------------------------------------------------------------------------
// Flash attention via mma.sync. CTA = 128 queries x 1 head. 8 warps x 16 rows.
// KV chunks of 64 keys, double-buffered cp.async, one sync per chunk.
// Output written in TILED split layout for the O-projection.
// ---------------------------------------------------------------------------
#define QT 128
#define TRB 144                       // smem tile row bytes (128 data + 16 pad)
#define TILEB (64 * TRB)              // 9216
#define STAGEB (4 * TILEB)            // 36864 (Khi,Klo,Vhi,Vlo)
#define ASMEM (2 * STAGEB + 512)

__device__ __forceinline__ void load_kv(
    uint32_t sb, int tid, int st, int c, size_t headoff,
    const int* __restrict__ attn_mask, int b)
{
#pragma unroll
    for (int i = 0; i < 8; i++) {
        const int idx = tid + i * 256;       // 0..2047
        const int t = idx >> 9;              // tile 0..3
        const int r = (idx >> 3) & 63;
        const int cc = idx & 7;
        const __nv_bfloat16* base =
            (t == 0) ? g_Khi : (t == 1) ? g_Klo : (t == 2) ? g_Vhi : g_Vlo;
        const __nv_bfloat16* src = base + headoff + (size_t)(c * 64 + r) * DH + cc * 8;
        cp16(sb + st * STAGEB + t * TILEB + r * TRB + cc * 16, src);
    }
    if (tid < 16)
        cp16(sb + 2 * STAGEB + st * 256 + tid * 16, attn_mask + b * SEQ + c * 64 + tid * 4);
    CP_COMMIT();
}

__global__ __launch_bounds__(256, 2)
void attn_mma_kernel(const int* __restrict__ attn_mask)
{
    extern __shared__ char smem[];
    const uint32_t sb = smem_u32(smem);
    const int tid = threadIdx.x;
    const int lane = tid & 31;
    const int wid = tid >> 5;
    const int qb = blockIdx.x;
    const int h = blockIdx.y;
    const int b = blockIdx.z;
    const int q0 = qb * QT;
    const size_t headoff = (size_t)(b * NH + h) * SEQ * DH;

    // ---- stage Q tile (hi/lo), read frags, then reuse buffers ----
#pragma unroll
    for (int i = 0; i < 8; i++) {
        const int idx = tid + i * 256;       // 0..2047
        const int t = idx >> 10;             // 0 hi, 1 lo
        const int r = (idx >> 3) & 127;
        const int cc = idx & 7;
        const __nv_bfloat16* base = t ? g_Qlo : g_Qhi;
        cp16(sb + t * 18432 + r * TRB + cc * 16,
             base + headoff + (size_t)(q0 + r) * DH + cc * 8);
    }
    CP_COMMIT();
    cp_wait<0>();
    __syncthreads();

    uint32_t qh[4][4], ql[4][4];
    {
        const int arow = wid * 16 + (lane & 15);
#pragma unroll
        for (int ks = 0; ks < 4; ks++) {
            const uint32_t off = (uint32_t)arow * TRB + (ks * 16 + 8 * ((lane >> 4) & 1)) * 2;
            ldsm_x4(qh[ks][0], qh[ks][1], qh[ks][2], qh[ks][3], sb + off);
            ldsm_x4(ql[ks][0], ql[ks][1], ql[ks][2], ql[ks][3], sb + 18432 + off);
        }
    }
    __syncthreads();   // done with Q staging area

    const int r0g = q0 + wid * 16 + (lane >> 2);
    const int r1g = r0g + 8;

    float m0r = -1e4f, m1r = -1e4f, l0 = 0.0f, l1 = 0.0f;
    float o[8][4];
#pragma unroll
    for (int j = 0; j < 8; j++)
#pragma unroll
        for (int v = 0; v < 4; v++) o[j][v] = 0.0f;

    const int clo = (2 * qb >= 8) ? (2 * qb - 8) : 0;
    const int chi = 2 * qb + 1;

    load_kv(sb, tid, 0, clo, headoff, attn_mask, b);

#pragma unroll 1
    for (int c = clo; c <= chi; c++) {
        const int st = (c - clo) & 1;
        cp_wait<0>();
        __syncthreads();   // chunk c visible; stage st^1 free
        if (c < chi)
            load_kv(sb, tid, st ^ 1, c + 1, headoff, attn_mask, b);

        const uint32_t kb = sb + st * STAGEB;

        // ---- S = Q K^T (3 split terms) ----
        float p[8][4];
#pragma unroll
        for (int j = 0; j < 8; j++)
#pragma unroll
            for (int v = 0; v < 4; v++) p[j][v] = 0.0f;

#pragma unroll
        for (int ks = 0; ks < 4; ks++) {
            uint32_t bh[8][2], bl[8][2];
#pragma unroll
            for (int jj = 0; jj < 4; jj++) {
                const int nrow = 16 * jj + 8 * ((lane >> 4) & 1) + (lane & 7);
                const int kcolb = (ks * 16 + 8 * ((lane >> 3) & 1)) * 2;
                const uint32_t off = (uint32_t)nrow * TRB + kcolb;
                ldsm_x4(bh[jj*2][0], bh[jj*2][1], bh[jj*2+1][0], bh[jj*2+1][1], kb + off);
                ldsm_x4(bl[jj*2][0], bl[jj*2][1], bl[jj*2+1][0], bl[jj*2+1][1], kb + TILEB + off);
            }
#pragma unroll
            for (int j = 0; j < 8; j++) {
                mma16816(p[j], qh[ks], bh[j]);
                mma16816(p[j], qh[ks], bl[j]);
                mma16816(p[j], ql[ks], bh[j]);
            }
        }

        // ---- mask + online softmax ----
        const int* mk = (const int*)(smem + 2 * STAGEB + st * 256);
        const int c64 = c * 64;
#pragma unroll
        for (int j = 0; j < 8; j++) {
            const int kloc = j * 8 + 2 * (lane & 3);
            const int kg = c64 + kloc;
            const int mv0 = mk[kloc], mv1 = mk[kloc + 1];
            if (!(kg     <= r0g && kg     >= r0g - (WIN-1) && mv0)) p[j][0] = -1e30f;
            if (!(kg + 1 <= r0g && kg + 1 >= r0g - (WIN-1) && mv1)) p[j][1] = -1e30f;
            if (!(kg     <= r1g && kg     >= r1g - (WIN-1) && mv0)) p[j][2] = -1e30f;
            if (!(kg + 1 <= r1g && kg + 1 >= r1g - (WIN-1) && mv1)) p[j][3] = -1e30f;
        }
        float mx0 = -1e30f, mx1 = -1e30f;
#pragma unroll
        for (int j = 0; j < 8; j++) {
            mx0 = fmaxf(mx0, fmaxf(p[j][0], p[j][1]));
            mx1 = fmaxf(mx1, fmaxf(p[j][2], p[j][3]));
        }
        mx0 = fmaxf(mx0, __shfl_xor_sync(0xffffffffu, mx0, 1));
        mx0 = fmaxf(mx0, __shfl_xor_sync(0xffffffffu, mx0, 2));
        mx1 = fmaxf(mx1, __shfl_xor_sync(0xffffffffu, mx1, 1));
        mx1 = fmaxf(mx1, __shfl_xor_sync(0xffffffffu, mx1, 2));

        const float mn0 = fmaxf(m0r, mx0);
        const float mn1 = fmaxf(m1r, mx1);
        const float cr0 = __expf(m0r - mn0);
        const float cr1 = __expf(m1r - mn1);
        m0r = mn0; m1r = mn1;
        l0 *= cr0; l1 *= cr1;
#pragma unroll
        for (int j = 0; j < 8; j++) {
            o[j][0] *= cr0; o[j][1] *= cr0;
            o[j][2] *= cr1; o[j][3] *= cr1;
        }
        float s0 = 0.0f, s1 = 0.0f;
#pragma unroll
        for (int j = 0; j < 8; j++) {
            p[j][0] = __expf(p[j][0] - mn0); s0 += p[j][0];
            p[j][1] = __expf(p[j][1] - mn0); s0 += p[j][1];
            p[j][2] = __expf(p[j][2] - mn1); s1 += p[j][2];
            p[j][3] = __expf(p[j][3] - mn1); s1 += p[j][3];
        }
        // quad-reduce the denominator partial sums (O sums over all quad keys)
        s0 += __shfl_xor_sync(0xffffffffu, s0, 1);
        s0 += __shfl_xor_sync(0xffffffffu, s0, 2);
        s1 += __shfl_xor_sync(0xffffffffu, s1, 1);
        s1 += __shfl_xor_sync(0xffffffffu, s1, 2);
        l0 += s0; l1 += s1;

        // ---- O += P V (3 split terms) ----
#pragma unroll
        for (int ks2 = 0; ks2 < 4; ks2++) {
            uint32_t ahp[4], alp[4];
            {
                const float p00 = p[2*ks2][0],   p01 = p[2*ks2][1];
                const float p02 = p[2*ks2][2],   p03 = p[2*ks2][3];
                const float p10 = p[2*ks2+1][0], p11 = p[2*ks2+1][1];
                const float p12 = p[2*ks2+1][2], p13 = p[2*ks2+1][3];
                ahp[0] = bfpack(p00, p01);
                ahp[1] = bfpack(p02, p03);
                ahp[2] = bfpack(p10, p11);
                ahp[3] = bfpack(p12, p13);
                const __nv_bfloat162* hp0 = (const __nv_bfloat162*)&ahp[0];
                const __nv_bfloat162* hp1 = (const __nv_bfloat162*)&ahp[1];
                const __nv_bfloat162* hp2 = (const __nv_bfloat162*)&ahp[2];
                const __nv_bfloat162* hp3 = (const __nv_bfloat162*)&ahp[3];
                alp[0] = bfpack(p00 - __bfloat162float(hp0->x), p01 - __bfloat162float(hp0->y));
                alp[1] = bfpack(p02 - __bfloat162float(hp1->x), p03 - __bfloat162float(hp1->y));
                alp[2] = bfpack(p10 - __bfloat162float(hp2->x), p11 - __bfloat162float(hp2->y));
                alp[3] = bfpack(p12 - __bfloat162float(hp3->x), p13 - __bfloat162float(hp3->y));
            }
            uint32_t bvh[8][2], bvl[8][2];
#pragma unroll
            for (int jj = 0; jj < 4; jj++) {
                const int vrow = 16 * ks2 + (lane & 7) + 8 * ((lane >> 3) & 1);
                const int colb = (2 * jj + (lane >> 4)) * 16;
                const uint32_t off = (uint32_t)vrow * TRB + colb;
                ldsm_x4_t(bvh[jj*2][0], bvh[jj*2][1], bvh[jj*2+1][0], bvh[jj*2+1][1],
                          kb + 2 * TILEB + off);
                ldsm_x4_t(bvl[jj*2][0], bvl[jj*2][1], bvl[jj*2+1][0], bvl[jj*2+1][1],
                          kb + 3 * TILEB + off);
            }
#pragma unroll
            for (int j = 0; j < 8; j++) {
                mma16816(o[j], ahp, bvh[j]);
                mma16816(o[j], ahp, bvl[j]);
                mma16816(o[j], alp, bvh[j]);
            }
        }
        // no trailing sync — next iteration's barrier covers stage reuse
    }

    // ---- normalize + write bf16 hi/lo in TILED layout for oproj ----
    const float i0 = 1.0f / fmaxf(l0, 1e-30f);
    const float i1 = 1.0f / fmaxf(l1, 1e-30f);
    const int t0m = b * SEQ + r0g;               // global token index
    const int mb = t0m >> 7;
    const int rit = t0m & 127;                   // row-in-tile (r1g = rit+8, same tile)
    char* tbaseH = g_AhiT + (size_t)mb * NCH * TILEBYTES;
    char* tbaseL = g_AloT + (size_t)mb * NCH * TILEBYTES;
#pragma unroll
    for (int j = 0; j < 8; j++) {
        const int k = h * DH + j * 8 + 2 * (lane & 3);
        const int kc = k >> 5;
        const uint32_t off0 = (uint32_t)kc * TILEBYTES + (uint32_t)rit * 80 + (k & 31) * 2;
        const uint32_t off1 = off0 + 8 * 80;
        float a0 = o[j][0] * i0, a1 = o[j][1] * i0;
        float a2 = o[j][2] * i1, a3 = o[j][3] * i1;
        __nv_bfloat16 h0 = __float2bfloat16(a0), h1 = __float2bfloat16(a1);
        __nv_bfloat16 h2 = __float2bfloat16(a2), h3 = __float2bfloat16(a3);
        ushort2 u0, u1, v0, v1;
        u0.x = __bfloat16_as_ushort(h0); u0.y = __bfloat16_as_ushort(h1);
        u1.x = __bfloat16_as_ushort(h2); u1.y = __bfloat16_as_ushort(h3);
        v0.x = __bfloat16_as_ushort(__float2bfloat16(a0 - __bfloat162float(h0)));
        v0.y = __bfloat16_as_ushort(__float2bfloat16(a1 - __bfloat162float(h1)));
        v1.x = __bfloat16_as_ushort(__float2bfloat16(a2 - __bfloat162float(h2)));
        v1.y = __bfloat16_as_ushort(__float2bfloat16(a3 - __bfloat162float(h3)));
        *(ushort2*)(tbaseH + off0) = u0;
        *(ushort2*)(tbaseH + off1) = u1;
        *(ushort2*)(tbaseL + off0) = v0;
        *(ushort2*)(tbaseL + off1) = v1;
    }
}

// ---------------------------------------------------------------------------
// Launch
// ---------------------------------------------------------------------------
extern "C" void kernel_launch(void* const* d_in, const int* in_sizes, int n_in,
                              void* d_out, int out_size)
{
    const float* x    = (const float*)d_in[0];
    const int*   mask = (const int*)  d_in[1];
    const float* Wq   = (const float*)d_in[2];
    const float* Wk   = (const float*)d_in[3];
    const float* Wv   = (const float*)d_in[4];
    const float* Wo   = (const float*)d_in[5];
    float* out = (float*)d_out;

    static bool attr_set = false;
    if (!attr_set) {
        cudaFuncSetAttribute(qkv_mma_kernel,   cudaFuncAttributeMaxDynamicSharedMemorySize, GSMEM);
        cudaFuncSetAttribute(oproj_mma_kernel, cudaFuncAttributeMaxDynamicSharedMemorySize, GSMEM);
        cudaFuncSetAttribute(attn_mma_kernel,  cudaFuncAttributeMaxDynamicSharedMemorySize, ASMEM);
        attr_set = true;
    }

    // X tiles (2048) + W tiles (4*256)
    split_kernel<<<NMB * NCH + 4 * NNB * NCH, 256>>>(x, Wq, Wk, Wv, Wo);

    dim3 qgrid(MTOT / BM, HID / BN, 3);
    qkv_mma_kernel<<<qgrid, GTHREADS, GSMEM>>>();

    dim3 agrid(SEQ / QT, NH, BATCH);
    attn_mma_kernel<<<agrid, 256, ASMEM>>>(mask);

    dim3 ogrid(MTOT / BM, HID / BN, 1);
    oproj_mma_kernel<<<ogrid, GTHREADS, GSMEM>>>(out);
}

// round 16
// speedup vs baseline: 1.2352x; 1.0280x over previous
#include <cuda_runtime.h>
#include <cuda_bf16.h>
#include <math.h>
#include <stdint.h>

// Problem constants
#define HID   1024
#define NH    16
#define DH    64
#define SEQ   4096
#define BATCH 2
#define WIN   512
#define MTOT  (BATCH*SEQ)          // 8192 tokens
#define XELEMS ((size_t)MTOT*HID)

// GEMM tiled operand layout: tile = 128 rows x 32 k-cols, 80B padded rows.
#define TILEBYTES 10240
#define NCH 32
#define NMB 64
#define NNB 8

// K/V attention tile images (144B padded rows, = attn smem layout)
#define KTILEB 9216                // 64 rows * 144
#define NKTILES 64                 // SEQ / 64

// ---------------------------------------------------------------------------
// Scratch (__device__ globals; no allocations allowed)
// ---------------------------------------------------------------------------
__device__ char g_XhiT[(size_t)NMB * NCH * TILEBYTES];
__device__ char g_XloT[(size_t)NMB * NCH * TILEBYTES];
__device__ char g_WhiT[(size_t)4 * NNB * NCH * TILEBYTES];
__device__ char g_WloT[(size_t)4 * NNB * NCH * TILEBYTES];
__device__ char g_AhiT[(size_t)NMB * NCH * TILEBYTES];
__device__ char g_AloT[(size_t)NMB * NCH * TILEBYTES];
// Q in [b,h,s,d] (round-13 proven path), pre-scaled by 1/8
__device__ __nv_bfloat16 g_Qhi[XELEMS];
__device__ __nv_bfloat16 g_Qlo[XELEMS];
// K/V as 64x144B tile images
__device__ char g_KhiI[(size_t)BATCH * NH * NKTILES * KTILEB];
__device__ char g_KloI[(size_t)BATCH * NH * NKTILES * KTILEB];
__device__ char g_VhiI[(size_t)BATCH * NH * NKTILES * KTILEB];
__device__ char g_VloI[(size_t)BATCH * NH * NKTILES * KTILEB];

// ---------------------------------------------------------------------------
// PTX helpers (baseline PTX only — compute_103-safe)
// ---------------------------------------------------------------------------
__device__ __forceinline__ uint32_t smem_u32(const void* p) {
    uint32_t a;
    asm("{ .reg .u64 t; cvta.to.shared.u64 t, %1; cvt.u32.u64 %0, t; }" : "=r"(a) : "l"(p));
    return a;
}
__device__ __forceinline__ void cp16(uint32_t dst, const void* src) {
    asm volatile("cp.async.cg.shared.global [%0], [%1], 16;" :: "r"(dst), "l"(src));
}
#define CP_COMMIT() asm volatile("cp.async.commit_group;" ::: "memory")
template <int N>
__device__ __forceinline__ void cp_wait() {
    asm volatile("cp.async.wait_group %0;" :: "n"(N) : "memory");
}
__device__ __forceinline__ void ldsm_x4(uint32_t& r0, uint32_t& r1, uint32_t& r2, uint32_t& r3, uint32_t a) {
    asm volatile("ldmatrix.sync.aligned.m8n8.x4.shared.b16 {%0,%1,%2,%3}, [%4];"
                 : "=r"(r0), "=r"(r1), "=r"(r2), "=r"(r3) : "r"(a));
}
__device__ __forceinline__ void ldsm_x4_t(uint32_t& r0, uint32_t& r1, uint32_t& r2, uint32_t& r3, uint32_t a) {
    asm volatile("ldmatrix.sync.aligned.m8n8.x4.trans.shared.b16 {%0,%1,%2,%3}, [%4];"
                 : "=r"(r0), "=r"(r1), "=r"(r2), "=r"(r3) : "r"(a));
}
__device__ __forceinline__ void mma16816(float* c, const uint32_t* a, const uint32_t* b) {
    asm volatile(
        "mma.sync.aligned.m16n8k16.row.col.f32.bf16.bf16.f32 "
        "{%0,%1,%2,%3}, {%4,%5,%6,%7}, {%8,%9}, {%0,%1,%2,%3};"
        : "+f"(c[0]), "+f"(c[1]), "+f"(c[2]), "+f"(c[3])
        : "r"(a[0]), "r"(a[1]), "r"(a[2]), "r"(a[3]), "r"(b[0]), "r"(b[1]));
}
__device__ __forceinline__ uint32_t bfpack(float a, float b) {
    uint32_t r;
    asm("cvt.rn.bf16x2.f32 %0, %1, %2;" : "=r"(r) : "f"(b), "f"(a));
    return r;
}
// --- bulk-copy (1D TMA) + mbarrier ---
#define MBAR_INIT(a, n) asm volatile("mbarrier.init.shared.b64 [%0], %1;" :: "r"(a), "r"(n) : "memory")
#define FENCE_ASYNC()   asm volatile("fence.proxy.async.shared::cta;" ::: "memory")
__device__ __forceinline__ void mbar_expect_tx(uint32_t mbar, uint32_t bytes) {
    asm volatile("mbarrier.arrive.expect_tx.shared.b64 _, [%0], %1;" :: "r"(mbar), "r"(bytes) : "memory");
}
__device__ __forceinline__ void bulk_cp(uint32_t dst, const void* src, uint32_t bytes, uint32_t mbar) {
    asm volatile("cp.async.bulk.shared::cta.global.mbarrier::complete_tx::bytes [%0], [%1], %2, [%3];"
                 :: "r"(dst), "l"(src), "r"(bytes), "r"(mbar) : "memory");
}
__device__ __forceinline__ void mbar_wait(uint32_t addr, uint32_t parity) {
    asm volatile(
        "{ .reg .pred P1;\n"
        "W%=: mbarrier.try_wait.parity.acquire.cta.shared::cta.b64 P1, [%0], %1;\n"
        "@P1 bra.uni D%=;\n bra.uni W%=;\n D%=: }"
        :: "r"(addr), "r"(parity) : "memory");
}

// ---------------------------------------------------------------------------
// fp32 -> bf16 hi/lo split of x and the 4 weight matrices, GEMM-TILED output.
// ---------------------------------------------------------------------------
__global__ __launch_bounds__(256)
void split_kernel(const float* __restrict__ x,
                  const float* __restrict__ Wq, const float* __restrict__ Wk,
                  const float* __restrict__ Wv, const float* __restrict__ Wo)
{
    const int bid = blockIdx.x;
    const int tid = threadIdx.x;
    const int c4 = (tid & 7) * 4;

    const float* srcbase;
    char *dh, *dl;
    if (bid < NMB * NCH) {
        const int mb = bid >> 5, kc = bid & 31;
        srcbase = x + (size_t)(mb * 128) * HID + kc * 32;
        dh = g_XhiT + (size_t)bid * TILEBYTES;
        dl = g_XloT + (size_t)bid * TILEBYTES;
    } else {
        const int wb = bid - NMB * NCH;
        const int w = wb >> 8;
        const int rem = wb & 255;
        const int nb = rem >> 5, kc = rem & 31;
        const float* Ws[4] = {Wq, Wk, Wv, Wo};
        srcbase = Ws[w] + (size_t)(nb * 128) * HID + kc * 32;
        dh = g_WhiT + (size_t)wb * TILEBYTES;
        dl = g_WloT + (size_t)wb * TILEBYTES;
    }
#pragma unroll
    for (int i = 0; i < 4; i++) {
        const int r = (tid >> 3) + i * 32;
        float4 v = *(const float4*)(srcbase + (size_t)r * HID + c4);
        __nv_bfloat16 h0 = __float2bfloat16(v.x), h1 = __float2bfloat16(v.y);
        __nv_bfloat16 h2 = __float2bfloat16(v.z), h3 = __float2bfloat16(v.w);
        ushort4 uh, ul;
        uh.x = __bfloat16_as_ushort(h0); uh.y = __bfloat16_as_ushort(h1);
        uh.z = __bfloat16_as_ushort(h2); uh.w = __bfloat16_as_ushort(h3);
        ul.x = __bfloat16_as_ushort(__float2bfloat16(v.x - __bfloat162float(h0)));
        ul.y = __bfloat16_as_ushort(__float2bfloat16(v.y - __bfloat162float(h1)));
        ul.z = __bfloat16_as_ushort(__float2bfloat16(v.z - __bfloat162float(h2)));
        ul.w = __bfloat16_as_ushort(__float2bfloat16(v.w - __bfloat162float(h3)));
        const uint32_t off = (uint32_t)r * 80 + c4 * 2;
        *(ushort4*)(dh + off) = uh;
        *(ushort4*)(dl + off) = ul;
    }
}

// ---------------------------------------------------------------------------
// bf16-split GEMM via mma.sync. 128x128 CTA, 128 threads, warp tile 64x64.
// Bulk-copy double-buffered pipeline.
// MODE 0: fp32 out. MODE 1: bf16 hi/lo to [b,h,s,d] arrays (Q).
// MODE 2: bf16 hi/lo to 64x144B K/V tile images.
// ---------------------------------------------------------------------------
#define BM 128
#define BN 128
#define RSB 80
#define TSB TILEBYTES
#define BUFB (4 * TSB)
#define GSMEM (2 * BUFB + 64)
#define GTHREADS 128

template <int MODE>
__device__ __forceinline__ void gemm_body(
    const char* __restrict__ AhiT, const char* __restrict__ AloT,
    const char* __restrict__ BhiT, const char* __restrict__ BloT,
    float* __restrict__ C, char* __restrict__ Chi,
    char* __restrict__ Clo, float scale)
{
    extern __shared__ char smem[];
    const uint32_t sb = smem_u32(smem);
    const int tid = threadIdx.x;
    const int lane = tid & 31;
    const int wid = tid >> 5;
    const int wm0 = (wid & 1) * 64;
    const int wn0 = (wid >> 1) * 64;
    const int m0 = blockIdx.x * BM;
    const int n0 = blockIdx.y * BN;
    const size_t atb = (size_t)(m0 >> 7) * NCH;
    const size_t btb = (size_t)(n0 >> 7) * NCH;
    const uint32_t mb0 = sb + 2 * BUFB;

    if (tid == 0) { MBAR_INIT(mb0, 1); MBAR_INIT(mb0 + 8, 1); }
    FENCE_ASYNC();
    __syncthreads();

    float acc[4][8][4];
#pragma unroll
    for (int i = 0; i < 4; i++)
#pragma unroll
        for (int j = 0; j < 8; j++)
#pragma unroll
            for (int v = 0; v < 4; v++) acc[i][j][v] = 0.0f;

    if (tid == 0) {
        mbar_expect_tx(mb0, BUFB);
        bulk_cp(sb,           AhiT + (atb + 0) * TILEBYTES, TILEBYTES, mb0);
        bulk_cp(sb + TSB,     AloT + (atb + 0) * TILEBYTES, TILEBYTES, mb0);
        bulk_cp(sb + 2 * TSB, BhiT + (btb + 0) * TILEBYTES, TILEBYTES, mb0);
        bulk_cp(sb + 3 * TSB, BloT + (btb + 0) * TILEBYTES, TILEBYTES, mb0);
    }

    int ph0 = 0, ph1 = 0;

#pragma unroll 1
    for (int ch = 0; ch < NCH; ch++) {
        const int buf = ch & 1;
        if (buf == 0) { mbar_wait(mb0, ph0); ph0 ^= 1; }
        else          { mbar_wait(mb0 + 8, ph1); ph1 ^= 1; }
        __syncthreads();
        if (tid == 0 && ch + 1 < NCH) {
            const uint32_t nbuf = sb + (buf ^ 1) * BUFB;
            const uint32_t nm = mb0 + (buf ^ 1) * 8;
            mbar_expect_tx(nm, BUFB);
            bulk_cp(nbuf,           AhiT + (atb + ch + 1) * TILEBYTES, TILEBYTES, nm);
            bulk_cp(nbuf + TSB,     AloT + (atb + ch + 1) * TILEBYTES, TILEBYTES, nm);
            bulk_cp(nbuf + 2 * TSB, BhiT + (btb + ch + 1) * TILEBYTES, TILEBYTES, nm);
            bulk_cp(nbuf + 3 * TSB, BloT + (btb + ch + 1) * TILEBYTES, TILEBYTES, nm);
        }

        const uint32_t sbuf = sb + buf * BUFB;
        const uint32_t sAh = sbuf;
        const uint32_t sAl = sbuf + TSB;
        const uint32_t sBh = sbuf + 2 * TSB;
        const uint32_t sBl = sbuf + 3 * TSB;

#pragma unroll
        for (int ks = 0; ks < 2; ks++) {
            const int arow = wm0 + (lane & 15);
            const int acolb = (ks * 16 + 8 * ((lane >> 4) & 1)) * 2;
            uint32_t ah[4][4], al[4][4];
#pragma unroll
            for (int i = 0; i < 4; i++) {
                const uint32_t off = (uint32_t)(arow + i * 16) * RSB + acolb;
                ldsm_x4(ah[i][0], ah[i][1], ah[i][2], ah[i][3], sAh + off);
                ldsm_x4(al[i][0], al[i][1], al[i][2], al[i][3], sAl + off);
            }
            uint32_t bh[8][2], bl[8][2];
#pragma unroll
            for (int jj = 0; jj < 4; jj++) {
                const int nrow = wn0 + 8 * (jj * 2 + ((lane >> 4) & 1)) + (lane & 7);
                const int kcolb = (ks * 16 + 8 * ((lane >> 3) & 1)) * 2;
                const uint32_t off = (uint32_t)nrow * RSB + kcolb;
                ldsm_x4(bh[jj*2][0], bh[jj*2][1], bh[jj*2+1][0], bh[jj*2+1][1], sBh + off);
                ldsm_x4(bl[jj*2][0], bl[jj*2][1], bl[jj*2+1][0], bl[jj*2+1][1], sBl + off);
            }
#pragma unroll
            for (int i = 0; i < 4; i++)
#pragma unroll
                for (int j = 0; j < 8; j++) {
                    mma16816(acc[i][j], ah[i], bh[j]);
                    mma16816(acc[i][j], ah[i], bl[j]);
                    mma16816(acc[i][j], al[i], bh[j]);
                }
        }
    }

    const int frow = lane >> 2;
    const int fcol = 2 * (lane & 3);
#pragma unroll
    for (int i = 0; i < 4; i++) {
#pragma unroll
        for (int j = 0; j < 8; j++) {
            const int m = m0 + wm0 + i * 16 + frow;
            const int n = n0 + wn0 + j * 8 + fcol;
            if (MODE == 0) {
                float* cp = C + (size_t)m * HID + n;
                *(float2*)cp = make_float2(acc[i][j][0], acc[i][j][1]);
                *(float2*)(cp + 8 * HID) = make_float2(acc[i][j][2], acc[i][j][3]);
            } else {
                const int b = m >> 12, s = m & (SEQ - 1);
                const int h = n >> 6, d = n & 63;
                float c0 = acc[i][j][0] * scale, c1 = acc[i][j][1] * scale;
                float c2 = acc[i][j][2] * scale, c3 = acc[i][j][3] * scale;
                __nv_bfloat16 h0 = __float2bfloat16(c0), h1 = __float2bfloat16(c1);
                __nv_bfloat16 h2 = __float2bfloat16(c2), h3 = __float2bfloat16(c3);
                ushort2 u0, u1, v0, v1;
                u0.x = __bfloat16_as_ushort(h0); u0.y = __bfloat16_as_ushort(h1);
                u1.x = __bfloat16_as_ushort(h2); u1.y = __bfloat16_as_ushort(h3);
                v0.x = __bfloat16_as_ushort(__float2bfloat16(c0 - __bfloat162float(h0)));
                v0.y = __bfloat16_as_ushort(__float2bfloat16(c1 - __bfloat162float(h1)));
                v1.x = __bfloat16_as_ushort(__float2bfloat16(c2 - __bfloat162float(h2)));
                v1.y = __bfloat16_as_ushort(__float2bfloat16(c3 - __bfloat162float(h3)));
                if (MODE == 1) {
                    __nv_bfloat16* Ch = (__nv_bfloat16*)Chi;
                    __nv_bfloat16* Cl = (__nv_bfloat16*)Clo;
                    const size_t base0 = (((size_t)(b * NH + h) * SEQ + s) * DH) + d;
                    const size_t base1 = base0 + 8 * DH;
                    *(ushort2*)(Ch + base0) = u0;
                    *(ushort2*)(Ch + base1) = u1;
                    *(ushort2*)(Cl + base0) = v0;
                    *(ushort2*)(Cl + base1) = v1;
                } else {
                    const size_t tile = (size_t)(b * NH + h) * NKTILES + (s >> 6);
                    const uint32_t ro = (uint32_t)(s & 63) * 144 + d * 2;
                    char* dh = Chi + tile * KTILEB + ro;
                    char* dl = Clo + tile * KTILEB + ro;
                    *(ushort2*)(dh)           = u0;
                    *(ushort2*)(dh + 8 * 144) = u1;
                    *(ushort2*)(dl)           = v0;
                    *(ushort2*)(dl + 8 * 144) = v1;
                }
            }
        }
    }
}

__global__ __launch_bounds__(GTHREADS, 2)
void qkv_mma_kernel()
{
    const int z = blockIdx.z;
    const size_t wsz = (size_t)NNB * NCH * TILEBYTES;
    if (z == 0)
        gemm_body<1>(g_XhiT, g_XloT, g_WhiT, g_WloT,
                     nullptr, (char*)g_Qhi, (char*)g_Qlo, 0.125f);
    else if (z == 1)
        gemm_body<2>(g_XhiT, g_XloT, g_WhiT + wsz, g_WloT + wsz,
                     nullptr, g_KhiI, g_KloI, 1.0f);
    else
        gemm_body<2>(g_XhiT, g_XloT, g_WhiT + 2 * wsz, g_WloT + 2 * wsz,
                     nullptr, g_VhiI, g_VloI, 1.0f);
}

__global__ __launch_bounds__(GTHREADS, 2)
void oproj_mma_kernel(float* __restrict__ out)
{
    const size_t wsz = (size_t)NNB * NCH * TILEBYTES;
    gemm_body<0>(g_AhiT, g_AloT, g_WhiT + 3 * wsz, g_WloT + 3 * wsz,
                 out, nullptr, nullptr, 1.0f);
}

// ---------------------------------------------------------------------------
// Flash attention via mma.sync. CTA = 128 queries x 1 head. 8 warps x 16 rows.
// Q staged via cp16; KV chunks via bulk-copied tile images.
// Output written in GEMM-tiled split layout for the O-projection.
// ---------------------------------------------------------------------------
#define QT 128
#define TRB 144
#define TILEB (64 * TRB)              // 9216 == KTILEB
#define STAGEB (4 * TILEB)            // 36864 (Khi,Klo,Vhi,Vlo)
#define ASMEM (2 * STAGEB + 512 + 64)

__global__ __launch_bounds__(256, 2)
void attn_mma_kernel(const int* __restrict__ attn_mask)
{
    extern __shared__ char smem[];
    const uint32_t sb = smem_u32(smem);
    const int tid = threadIdx.x;
    const int lane = tid & 31;
    const int wid = tid >> 5;
    const int qb = blockIdx.x;
    const int h = blockIdx.y;
    const int b = blockIdx.z;
    const int q0 = qb * QT;
    const size_t bh = (size_t)(b * NH + h);
    const size_t headoff = bh * SEQ * DH;

    const char* KhiB = g_KhiI + bh * NKTILES * KTILEB;
    const char* KloB = g_KloI + bh * NKTILES * KTILEB;
    const char* VhiB = g_VhiI + bh * NKTILES * KTILEB;
    const char* VloB = g_VloI + bh * NKTILES * KTILEB;

    const uint32_t mbs0 = sb + 2 * STAGEB + 512;
    const uint32_t mbs1 = mbs0 + 8;

    if (tid == 0) { MBAR_INIT(mbs0, 1); MBAR_INIT(mbs1, 1); }
    FENCE_ASYNC();
    __syncthreads();

    // ---- stage Q tile (hi/lo) via cp16 from [b,h,s,d] ----
#pragma unroll
    for (int i = 0; i < 8; i++) {
        const int idx = tid + i * 256;       // 0..2047
        const int t = idx >> 10;             // 0 hi, 1 lo
        const int r = (idx >> 3) & 127;
        const int cc = idx & 7;
        const __nv_bfloat16* base = t ? g_Qlo : g_Qhi;
        cp16(sb + t * 18432 + r * TRB + cc * 16,
             base + headoff + (size_t)(q0 + r) * DH + cc * 8);
    }
    CP_COMMIT();
    cp_wait<0>();
    __syncthreads();

    uint32_t qh[4][4], ql[4][4];
    {
        const int arow = wid * 16 + (lane & 15);
#pragma unroll
        for (int ks = 0; ks < 4; ks++) {
            const uint32_t off = (uint32_t)arow * TRB + (ks * 16 + 8 * ((lane >> 4) & 1)) * 2;
            ldsm_x4(qh[ks][0], qh[ks][1], qh[ks][2], qh[ks][3], sb + off);
            ldsm_x4(ql[ks][0], ql[ks][1], ql[ks][2], ql[ks][3], sb + 18432 + off);
        }
    }
    __syncthreads();   // all warps done reading Q staging area

    const int r0g = q0 + wid * 16 + (lane >> 2);
    const int r1g = r0g + 8;

    float m0r = -1e4f, m1r = -1e4f, l0 = 0.0f, l1 = 0.0f;
    float o[8][4];
#pragma unroll
    for (int j = 0; j < 8; j++)
#pragma unroll
        for (int v = 0; v < 4; v++) o[j][v] = 0.0f;

    const int clo = (2 * qb >= 8) ? (2 * qb - 8) : 0;
    const int chi = 2 * qb + 1;

    // issue first chunk (stage 0)
    if (tid == 0) {
        mbar_expect_tx(mbs0, 4 * KTILEB);
        bulk_cp(sb,             KhiB + (size_t)clo * KTILEB, KTILEB, mbs0);
        bulk_cp(sb + TILEB,     KloB + (size_t)clo * KTILEB, KTILEB, mbs0);
        bulk_cp(sb + 2 * TILEB, VhiB + (size_t)clo * KTILEB, KTILEB, mbs0);
        bulk_cp(sb + 3 * TILEB, VloB + (size_t)clo * KTILEB, KTILEB, mbs0);
    }
    if (tid < 16)
        cp16(sb + 2 * STAGEB + tid * 16, attn_mask + b * SEQ + clo * 64 + tid * 4);
    CP_COMMIT();

    int phs[2] = {0, 0};

#pragma unroll 1
    for (int c = clo; c <= chi; c++) {
        const int st = (c - clo) & 1;
        mbar_wait(st == 0 ? mbs0 : mbs1, phs[st]);
        phs[st] ^= 1;
        cp_wait<0>();      // mask for this stage
        __syncthreads();   // stage st data + mask visible; stage st^1 consumed
        if (c < chi) {
            const uint32_t nb = sb + (st ^ 1) * STAGEB;
            const uint32_t nm = (st == 0) ? mbs1 : mbs0;
            if (tid == 0) {
                mbar_expect_tx(nm, 4 * KTILEB);
                bulk_cp(nb,             KhiB + (size_t)(c + 1) * KTILEB, KTILEB, nm);
                bulk_cp(nb + TILEB,     KloB + (size_t)(c + 1) * KTILEB, KTILEB, nm);
                bulk_cp(nb + 2 * TILEB, VhiB + (size_t)(c + 1) * KTILEB, KTILEB, nm);
                bulk_cp(nb + 3 * TILEB, VloB + (size_t)(c + 1) * KTILEB, KTILEB, nm);
            }
            if (tid < 16)   // FIX (round 14/15 bug): destination needs + tid*16
                cp16(sb + 2 * STAGEB + (st ^ 1) * 256 + tid * 16,
                     attn_mask + b * SEQ + (c + 1) * 64 + tid * 4);
            CP_COMMIT();
        }

        const uint32_t kb = sb + st * STAGEB;

        // ---- S = Q K^T (3 split terms) ----
        float p[8][4];
#pragma unroll
        for (int j = 0; j < 8; j++)
#pragma unroll
            for (int v = 0; v < 4; v++) p[j][v] = 0.0f;

#pragma unroll
        for (int ks = 0; ks < 4; ks++) {
            uint32_t bh2[8][2], bl2[8][2];
#pragma unroll
            for (int jj = 0; jj < 4; jj++) {
                const int nrow = 16 * jj + 8 * ((lane >> 4) & 1) + (lane & 7);
                const int kcolb = (ks * 16 + 8 * ((lane >> 3) & 1)) * 2;
                const uint32_t off = (uint32_t)nrow * TRB + kcolb;
                ldsm_x4(bh2[jj*2][0], bh2[jj*2][1], bh2[jj*2+1][0], bh2[jj*2+1][1], kb + off);
                ldsm_x4(bl2[jj*2][0], bl2[jj*2][1], bl2[jj*2+1][0], bl2[jj*2+1][1], kb + TILEB + off);
            }
#pragma unroll
            for (int j = 0; j < 8; j++) {
                mma16816(p[j], qh[ks], bh2[j]);
                mma16816(p[j], qh[ks], bl2[j]);
                mma16816(p[j], ql[ks], bh2[j]);
            }
        }

        // ---- mask + online softmax ----
        const int* mk = (const int*)(smem + 2 * STAGEB + st * 256);
        const int c64 = c * 64;
#pragma unroll
        for (int j = 0; j < 8; j++) {
            const int kloc = j * 8 + 2 * (lane & 3);
            const int kg = c64 + kloc;
            const int mv0 = mk[kloc], mv1 = mk[kloc + 1];
            if (!(kg     <= r0g && kg     >= r0g - (WIN-1) && mv0)) p[j][0] = -1e30f;
            if (!(kg + 1 <= r0g && kg + 1 >= r0g - (WIN-1) && mv1)) p[j][1] = -1e30f;
            if (!(kg     <= r1g && kg     >= r1g - (WIN-1) && mv0)) p[j][2] = -1e30f;
            if (!(kg + 1 <= r1g && kg + 1 >= r1g - (WIN-1) && mv1)) p[j][3] = -1e30f;
        }
        float mx0 = -1e30f, mx1 = -1e30f;
#pragma unroll
        for (int j = 0; j < 8; j++) {
            mx0 = fmaxf(mx0, fmaxf(p[j][0], p[j][1]));
            mx1 = fmaxf(mx1, fmaxf(p[j][2], p[j][3]));
        }
        mx0 = fmaxf(mx0, __shfl_xor_sync(0xffffffffu, mx0, 1));
        mx0 = fmaxf(mx0, __shfl_xor_sync(0xffffffffu, mx0, 2));
        mx1 = fmaxf(mx1, __shfl_xor_sync(0xffffffffu, mx1, 1));
        mx1 = fmaxf(mx1, __shfl_xor_sync(0xffffffffu, mx1, 2));

        const float mn0 = fmaxf(m0r, mx0);
        const float mn1 = fmaxf(m1r, mx1);
        const float cr0 = __expf(m0r - mn0);
        const float cr1 = __expf(m1r - mn1);
        m0r = mn0; m1r = mn1;
        l0 *= cr0; l1 *= cr1;
#pragma unroll
        for (int j = 0; j < 8; j++) {
            o[j][0] *= cr0; o[j][1] *= cr0;
            o[j][2] *= cr1; o[j][3] *= cr1;
        }
        float s0 = 0.0f, s1 = 0.0f;
#pragma unroll
        for (int j = 0; j < 8; j++) {
            p[j][0] = __expf(p[j][0] - mn0); s0 += p[j][0];
            p[j][1] = __expf(p[j][1] - mn0); s0 += p[j][1];
            p[j][2] = __expf(p[j][2] - mn1); s1 += p[j][2];
            p[j][3] = __expf(p[j][3] - mn1); s1 += p[j][3];
        }
        s0 += __shfl_xor_sync(0xffffffffu, s0, 1);
        s0 += __shfl_xor_sync(0xffffffffu, s0, 2);
        s1 += __shfl_xor_sync(0xffffffffu, s1, 1);
        s1 += __shfl_xor_sync(0xffffffffu, s1, 2);
        l0 += s0; l1 += s1;

        // ---- O += P V (3 split terms) ----
#pragma unroll
        for (int ks2 = 0; ks2 < 4; ks2++) {
            uint32_t ahp[4], alp[4];
            {
                const float p00 = p[2*ks2][0],   p01 = p[2*ks2][1];
                const float p02 = p[2*ks2][2],   p03 = p[2*ks2][3];
                const float p10 = p[2*ks2+1][0], p11 = p[2*ks2+1][1];
                const float p12 = p[2*ks2+1][2], p13 = p[2*ks2+1][3];
                ahp[0] = bfpack(p00, p01);
                ahp[1] = bfpack(p02, p03);
                ahp[2] = bfpack(p10, p11);
                ahp[3] = bfpack(p12, p13);
                const __nv_bfloat162* hp0 = (const __nv_bfloat162*)&ahp[0];
                const __nv_bfloat162* hp1 = (const __nv_bfloat162*)&ahp[1];
                const __nv_bfloat162* hp2 = (const __nv_bfloat162*)&ahp[2];
                const __nv_bfloat162* hp3 = (const __nv_bfloat162*)&ahp[3];
                alp[0] = bfpack(p00 - __bfloat162float(hp0->x), p01 - __bfloat162float(hp0->y));
                alp[1] = bfpack(p02 - __bfloat162float(hp1->x), p03 - __bfloat162float(hp1->y));
                alp[2] = bfpack(p10 - __bfloat162float(hp2->x), p11 - __bfloat162float(hp2->y));
                alp[3] = bfpack(p12 - __bfloat162float(hp3->x), p13 - __bfloat162float(hp3->y));
            }
            uint32_t bvh[8][2], bvl[8][2];
#pragma unroll
            for (int jj = 0; jj < 4; jj++) {
                const int vrow = 16 * ks2 + (lane & 7) + 8 * ((lane >> 3) & 1);
                const int colb = (2 * jj + (lane >> 4)) * 16;
                const uint32_t off = (uint32_t)vrow * TRB + colb;
                ldsm_x4_t(bvh[jj*2][0], bvh[jj*2][1], bvh[jj*2+1][0], bvh[jj*2+1][1],
                          kb + 2 * TILEB + off);
                ldsm_x4_t(bvl[jj*2][0], bvl[jj*2][1], bvl[jj*2+1][0], bvl[jj*2+1][1],
                          kb + 3 * TILEB + off);
            }
#pragma unroll
            for (int j = 0; j < 8; j++) {
                mma16816(o[j], ahp, bvh[j]);
                mma16816(o[j], ahp, bvl[j]);
                mma16816(o[j], alp, bvh[j]);
            }
        }
        // no trailing sync — next iteration's wait+sync covers stage reuse
    }

    // ---- normalize + write bf16 hi/lo in GEMM-tiled layout for oproj ----
    const float i0 = 1.0f / fmaxf(l0, 1e-30f);
    const float i1 = 1.0f / fmaxf(l1, 1e-30f);
    const int t0m = b * SEQ + r0g;
    const int mb = t0m >> 7;
    const int rit = t0m & 127;
    char* tbaseH = g_AhiT + (size_t)mb * NCH * TILEBYTES;
    char* tbaseL = g_AloT + (size_t)mb * NCH * TILEBYTES;
#pragma unroll
    for (int j = 0; j < 8; j++) {
        const int k = h * DH + j * 8 + 2 * (lane & 3);
        const int kc = k >> 5;
        const uint32_t off0 = (uint32_t)kc * TILEBYTES + (uint32_t)rit * 80 + (k & 31) * 2;
        const uint32_t off1 = off0 + 8 * 80;
        float a0 = o[j][0] * i0, a1 = o[j][1] * i0;
        float a2 = o[j][2] * i1, a3 = o[j][3] * i1;
        __nv_bfloat16 h0 = __float2bfloat16(a0), h1 = __float2bfloat16(a1);
        __nv_bfloat16 h2 = __float2bfloat16(a2), h3 = __float2bfloat16(a3);
        ushort2 u0, u1, v0, v1;
        u0.x = __bfloat16_as_ushort(h0); u0.y = __bfloat16_as_ushort(h1);
        u1.x = __bfloat16_as_ushort(h2); u1.y = __bfloat16_as_ushort(h3);
        v0.x = __bfloat16_as_ushort(__float2bfloat16(a0 - __bfloat162float(h0)));
        v0.y = __bfloat16_as_ushort(__float2bfloat16(a1 - __bfloat162float(h1)));
        v1.x = __bfloat16_as_ushort(__float2bfloat16(a2 - __bfloat162float(h2)));
        v1.y = __bfloat16_as_ushort(__float2bfloat16(a3 - __bfloat162float(h3)));
        *(ushort2*)(tbaseH + off0) = u0;
        *(ushort2*)(tbaseH + off1) = u1;
        *(ushort2*)(tbaseL + off0) = v0;
        *(ushort2*)(tbaseL + off1) = v1;
    }
}

// ---------------------------------------------------------------------------
// Launch
// ---------------------------------------------------------------------------
extern "C" void kernel_launch(void* const* d_in, const int* in_sizes, int n_in,
                              void* d_out, int out_size)
{
    const float* x    = (const float*)d_in[0];
    const int*   mask = (const int*)  d_in[1];
    const float* Wq   = (const float*)d_in[2];
    const float* Wk   = (const float*)d_in[3];
    const float* Wv   = (const float*)d_in[4];
    const float* Wo   = (const float*)d_in[5];
    float* out = (float*)d_out;

    static bool attr_set = false;
    if (!attr_set) {
        cudaFuncSetAttribute(qkv_mma_kernel,   cudaFuncAttributeMaxDynamicSharedMemorySize, GSMEM);
        cudaFuncSetAttribute(oproj_mma_kernel, cudaFuncAttributeMaxDynamicSharedMemorySize, GSMEM);
        cudaFuncSetAttribute(attn_mma_kernel,  cudaFuncAttributeMaxDynamicSharedMemorySize, ASMEM);
        attr_set = true;
    }

    split_kernel<<<NMB * NCH + 4 * NNB * NCH, 256>>>(x, Wq, Wk, Wv, Wo);

    dim3 qgrid(MTOT / BM, HID / BN, 3);
    qkv_mma_kernel<<<qgrid, GTHREADS, GSMEM>>>();

    dim3 agrid(SEQ / QT, NH, BATCH);
    attn_mma_kernel<<<agrid, 256, ASMEM>>>(mask);

    dim3 ogrid(MTOT / BM, HID / BN, 1);
    oproj_mma_kernel<<<ogrid, GTHREADS, GSMEM>>>(out);
}